// round 5
// baseline (speedup 1.0000x reference)
#include <cuda_runtime.h>
#include <math.h>

#define B 32
#define T 512
#define U 1024
#define E 1024
#define DIN 256
#define G4 4096        // 4*U
#define KX 1280        // DIN + E
#define TC 16          // T-split for context partials
#define TCH (T / TC)   // 32
#define KCH 128        // k-chunk for z GEMM
#define NSPL_B 10      // fused-gemm splits: 2 (inputs) + 8 (h)
#define NSPL_A 8       // k6a splits: 8 (context)
#define NSPL (NSPL_B + NSPL_A)
#define NGEMMB 80      // fused gemm blocks: (G4/512)=8 j-tiles x 10 kb

// ---------------- scratch (device globals: no allocations allowed) ----------
__device__ float g_qpart[16 * B * U];
__device__ float g_query[B * U];
__device__ float g_logits[B * T];
__device__ float g_attn[B * T];
__device__ float g_ctxpart[TC * B * E];
__device__ float g_context[B * E];
__device__ float g_zpart[NSPL * B * G4];

// ---------------- helpers ----------------------------------------------------
__device__ __forceinline__ unsigned long long pack2(float a, float b) {
    unsigned long long r;
    asm("mov.b64 %0, {%1, %2};" : "=l"(r) : "r"(__float_as_uint(a)), "r"(__float_as_uint(b)));
    return r;
}
__device__ __forceinline__ void unpack2(unsigned long long v, float& a, float& b) {
    unsigned int lo, hi;
    asm("mov.b64 {%0, %1}, %2;" : "=r"(lo), "=r"(hi) : "l"(v));
    a = __uint_as_float(lo); b = __uint_as_float(hi);
}
__device__ __forceinline__ unsigned long long fma2(unsigned long long x,
                                                   unsigned long long y,
                                                   unsigned long long a) {
    unsigned long long d;
    asm("fma.rn.f32x2 %0, %1, %2, %3;" : "=l"(d) : "l"(x), "l"(y), "l"(a));
    return d;
}
__device__ __forceinline__ float tanh_hw(float x) {
    float y;
    asm("tanh.approx.f32 %0, %1;" : "=f"(y) : "f"(x));
    return y;
}
__device__ __forceinline__ float sigmoid_acc(float x) {
    return 1.0f / (1.0f + expf(-x));
}

// ---------------- K1: query partial GEMM  (h[32,1024] @ Wa_w[1024,1024]) -----
__global__ void k1_query_partial(const float* __restrict__ h,
                                 const float* __restrict__ Wa) {
    __shared__ __align__(16) float hs[64 * 36];
    const int tid = threadIdx.x;
    const int u = blockIdx.x * 128 + tid;
    const int kb = blockIdx.y;
    const int k0 = kb * 64;

    for (int idx = tid; idx < 32 * 64; idx += 128) {
        int b = idx >> 6, k = idx & 63;
        hs[k * 36 + b] = h[b * U + k0 + k];
    }
    __syncthreads();

    unsigned long long acc[16];
#pragma unroll
    for (int p = 0; p < 16; p++) acc[p] = 0ull;

    const float* wcol = Wa + (size_t)k0 * U + u;
#pragma unroll 8
    for (int k = 0; k < 64; k++) {
        float w = wcol[(size_t)k * U];
        unsigned long long ww = pack2(w, w);
        const ulonglong2* xp = reinterpret_cast<const ulonglong2*>(&hs[k * 36]);
#pragma unroll
        for (int p = 0; p < 8; p++) {
            ulonglong2 x2 = xp[p];
            acc[2 * p]     = fma2(x2.x, ww, acc[2 * p]);
            acc[2 * p + 1] = fma2(x2.y, ww, acc[2 * p + 1]);
        }
    }

    float* outp = g_qpart + (size_t)kb * (B * U);
#pragma unroll
    for (int p = 0; p < 16; p++) {
        float a, b2; unpack2(acc[p], a, b2);
        outp[(2 * p) * U + u] = a;
        outp[(2 * p + 1) * U + u] = b2;
    }
}

// ---------------- K1b: reduce query partials + bias --------------------------
__global__ void k1b_query_reduce(const float* __restrict__ Wa_b) {
    int i = blockIdx.x * 256 + threadIdx.x;
    if (i >= B * U) return;
    float s = Wa_b[i & (U - 1)];
#pragma unroll
    for (int kb = 0; kb < 16; kb++) s += g_qpart[kb * (B * U) + i];
    g_query[i] = s;
}

// ---------------- K26: fused scores + independent z-GEMM half -----------------
// Blocks [0,80): z partials for inputs+h (512-thread j-tiles, 10 k-chunks).
// Blocks [80,80+1024): logits[b,t] = sum_u tanh(q+es)*va.
// GEMM blocks come FIRST so they co-schedule with score blocks in wave 1.
__global__ void __launch_bounds__(512) k26_fused(
    const float* __restrict__ es,
    const float* __restrict__ va_w,
    const float* __restrict__ va_b,
    const float* __restrict__ inputs,
    const float* __restrict__ h,
    const float* __restrict__ Wk,
    const float* __restrict__ Wr) {
    __shared__ __align__(16) float pool[KCH * 36];  // 18.4KB, reused by both roles
    const int tid = threadIdx.x;

    if (blockIdx.x < NGEMMB) {
        // ---- GEMM role ----
        const int bx = blockIdx.x;
        const int kb = bx / 8;         // 0..9
        const int j  = (bx & 7) * 512 + tid;
        const float* xsrc; int x_ld, xk0;
        const float* W;    int wk0;
        if (kb < 2) { xsrc = inputs; x_ld = DIN; xk0 = kb * KCH; W = Wk; wk0 = kb * KCH; }
        else        { xsrc = h;      x_ld = U;   xk0 = (kb - 2) * KCH; W = Wr; wk0 = (kb - 2) * KCH; }

        for (int idx = tid; idx < 32 * KCH; idx += 512) {
            int b = idx >> 7, kk = idx & (KCH - 1);
            pool[kk * 36 + b] = xsrc[(size_t)b * x_ld + xk0 + kk];
        }
        __syncthreads();

        unsigned long long acc[16];
#pragma unroll
        for (int p = 0; p < 16; p++) acc[p] = 0ull;

        const float* wcol = W + (size_t)wk0 * G4 + j;
#pragma unroll 8
        for (int kk = 0; kk < KCH; kk++) {
            float w = wcol[(size_t)kk * G4];
            unsigned long long ww = pack2(w, w);
            const ulonglong2* xp = reinterpret_cast<const ulonglong2*>(&pool[kk * 36]);
#pragma unroll
            for (int p = 0; p < 8; p++) {
                ulonglong2 x2 = xp[p];
                acc[2 * p]     = fma2(x2.x, ww, acc[2 * p]);
                acc[2 * p + 1] = fma2(x2.y, ww, acc[2 * p + 1]);
            }
        }

        float* outp = g_zpart + (size_t)kb * (B * G4);
#pragma unroll
        for (int p = 0; p < 16; p++) {
            float a, b2; unpack2(acc[p], a, b2);
            outp[(size_t)(2 * p) * G4 + j] = a;
            outp[(size_t)(2 * p + 1) * G4 + j] = b2;
        }
    } else {
        // ---- scores role ----
        const int bx = blockIdx.x - NGEMMB;
        const int b = bx >> 5;               // 32 score blocks per batch
        const int t = (bx & 31) * 16 + (tid >> 5);
        const int lane = tid & 31;

        float4* qs = reinterpret_cast<float4*>(pool);        // 256 float4
        float4* vs = qs + 256;                                // 256 float4

        if (tid < 256) qs[tid] = reinterpret_cast<const float4*>(g_query + b * U)[tid];
        else if (tid < 512) vs[tid - 256] = reinterpret_cast<const float4*>(va_w)[tid - 256];
        __syncthreads();

        const float4* esrow = reinterpret_cast<const float4*>(es + ((size_t)(b * T + t)) * U);
        float4 e[8];
#pragma unroll
        for (int i = 0; i < 8; i++) e[i] = esrow[lane + i * 32];

        float s = 0.f;
#pragma unroll
        for (int i = 0; i < 8; i++) {
            int u4 = lane + i * 32;
            float4 q4 = qs[u4];
            float4 v4 = vs[u4];
            s += tanh_hw(q4.x + e[i].x) * v4.x;
            s += tanh_hw(q4.y + e[i].y) * v4.y;
            s += tanh_hw(q4.z + e[i].z) * v4.z;
            s += tanh_hw(q4.w + e[i].w) * v4.w;
        }
#pragma unroll
        for (int o = 16; o; o >>= 1) s += __shfl_xor_sync(0xffffffffu, s, o);
        if (lane == 0) g_logits[b * T + t] = s + va_b[0];
    }
}

// ---------------- K3: softmax over T per batch (tiny) -------------------------
__global__ void k3_softmax() {
    __shared__ float red[16];
    const int tid = threadIdx.x;
    const int b = blockIdx.x;
    const int lane = tid & 31, wid = tid >> 5;

    float l = g_logits[b * T + tid];
    float m = l;
#pragma unroll
    for (int o = 16; o; o >>= 1) m = fmaxf(m, __shfl_xor_sync(0xffffffffu, m, o));
    if (lane == 0) red[wid] = m;
    __syncthreads();
    if (tid < 32) {
        float v = red[tid & 15];
#pragma unroll
        for (int o = 8; o; o >>= 1) v = fmaxf(v, __shfl_xor_sync(0xffffffffu, v, o));
        if (tid == 0) red[0] = v;
    }
    __syncthreads();
    float mx = red[0];
    float p = __expf(l - mx);
    float sum = p;
#pragma unroll
    for (int o = 16; o; o >>= 1) sum += __shfl_xor_sync(0xffffffffu, sum, o);
    __syncthreads();
    if (lane == 0) red[wid] = sum;
    __syncthreads();
    if (tid < 32) {
        float v = (tid < 16) ? red[tid] : 0.f;
#pragma unroll
        for (int o = 8; o; o >>= 1) v += __shfl_xor_sync(0xffffffffu, v, o);
        if (tid == 0) red[0] = v;
    }
    __syncthreads();
    g_attn[b * T + tid] = p / red[0];
}

// ---------------- K4: context partial (barrier-light, high MLP) ---------------
__global__ void k4_context(const float* __restrict__ se) {
    __shared__ float as[TCH];
    const int tid = threadIdx.x;
    const int b = blockIdx.x;
    const int e4 = blockIdx.y * 128 + tid;
    const int tc = blockIdx.z;

    if (tid < TCH) as[tid] = g_attn[b * T + tc * TCH + tid];
    __syncthreads();

    const float4* se4 = reinterpret_cast<const float4*>(se)
                      + ((size_t)(b * T + tc * TCH)) * 256 + e4;
    float4 acc = make_float4(0.f, 0.f, 0.f, 0.f);
#pragma unroll
    for (int t = 0; t < TCH; t++) {
        float p = as[t];
        float4 v = se4[(size_t)t * 256];
        acc.x += p * v.x; acc.y += p * v.y; acc.z += p * v.z; acc.w += p * v.w;
    }
    reinterpret_cast<float4*>(g_ctxpart)[(size_t)(tc * B + b) * 256 + e4] = acc;
}

// ---------------- K5: reduce context partials ---------------------------------
__global__ void k5_ctx_reduce() {
    int i = blockIdx.x * 256 + threadIdx.x;
    if (i >= B * E) return;
    float s = 0.f;
#pragma unroll
    for (int tc = 0; tc < TC; tc++) s += g_ctxpart[tc * (B * E) + i];
    g_context[i] = s;
}

// ---------------- K6a: z partials for context (critical path) -----------------
__global__ void k6a_z_ctx(const float* __restrict__ Wk) {
    __shared__ __align__(16) float xs[KCH * 36];
    const int tid = threadIdx.x;
    const int j = blockIdx.x * 128 + tid;
    const int kb = blockIdx.y;
    const int k0 = kb * KCH;

    for (int idx = tid; idx < 32 * KCH; idx += 128) {
        int b = idx >> 7, kk = idx & (KCH - 1);
        xs[kk * 36 + b] = g_context[(size_t)b * E + k0 + kk];
    }
    __syncthreads();

    unsigned long long acc[16];
#pragma unroll
    for (int p = 0; p < 16; p++) acc[p] = 0ull;

    const float* wcol = Wk + (size_t)(DIN + k0) * G4 + j;
#pragma unroll 8
    for (int kk = 0; kk < KCH; kk++) {
        float w = wcol[(size_t)kk * G4];
        unsigned long long ww = pack2(w, w);
        const ulonglong2* xp = reinterpret_cast<const ulonglong2*>(&xs[kk * 36]);
#pragma unroll
        for (int p = 0; p < 8; p++) {
            ulonglong2 x2 = xp[p];
            acc[2 * p]     = fma2(x2.x, ww, acc[2 * p]);
            acc[2 * p + 1] = fma2(x2.y, ww, acc[2 * p + 1]);
        }
    }

    float* outp = g_zpart + (size_t)(NSPL_B + kb) * (B * G4);
#pragma unroll
    for (int p = 0; p < 16; p++) {
        float a, b2; unpack2(acc[p], a, b2);
        outp[(size_t)(2 * p) * G4 + j] = a;
        outp[(size_t)(2 * p + 1) * G4 + j] = b2;
    }
}

// ---------------- K7: reduce z partials + bias, gates, outputs ----------------
__global__ void k7_gates(const float* __restrict__ c,
                         const float* __restrict__ bias,
                         float* __restrict__ out) {
    int i = blockIdx.x * 128 + threadIdx.x;
    if (i >= B * U) return;
    int b = i >> 10, u = i & (U - 1);

    float z[4];
#pragma unroll
    for (int g = 0; g < 4; g++) {
        int col = g * U + u;
        float s = bias[col];
        const float* zp = g_zpart + (size_t)b * G4 + col;
#pragma unroll
        for (int kb = 0; kb < NSPL; kb++)
            s += zp[(size_t)kb * (B * G4)];
        z[g] = s;
    }

    float c_new = sigmoid_acc(z[1]) * c[i] + sigmoid_acc(z[0]) * tanhf(z[2]);
    float h_new = sigmoid_acc(z[3]) * tanhf(c_new);

    out[i]                = h_new;  // lstmout
    out[B * U + i]        = h_new;  // h state
    out[2 * B * U + i]    = c_new;  // c state
}

// ---------------- launcher ------------------------------------------------------
extern "C" void kernel_launch(void* const* d_in, const int* in_sizes, int n_in,
                              void* d_out, int out_size) {
    const float* inputs      = (const float*)d_in[0];
    const float* h           = (const float*)d_in[1];
    const float* c           = (const float*)d_in[2];
    const float* speech_enc  = (const float*)d_in[3];
    const float* encodestate = (const float*)d_in[4];
    const float* Wa_w        = (const float*)d_in[5];
    const float* Wa_b        = (const float*)d_in[6];
    const float* va_w        = (const float*)d_in[7];
    const float* va_b        = (const float*)d_in[8];
    const float* kernel_w    = (const float*)d_in[9];
    const float* rec_kernel  = (const float*)d_in[10];
    const float* bias        = (const float*)d_in[11];
    float* out = (float*)d_out;

    k1_query_partial<<<dim3(U / 128, 16), 128>>>(h, Wa_w);
    k1b_query_reduce<<<(B * U + 255) / 256, 256>>>(Wa_b);
    k26_fused<<<NGEMMB + 1024, 512>>>(encodestate, va_w, va_b,
                                      inputs, h, kernel_w, rec_kernel);
    k3_softmax<<<B, T>>>();
    k4_context<<<dim3(B, 2, TC), 128>>>(speech_enc);
    k5_ctx_reduce<<<(B * E + 255) / 256, 256>>>();
    k6a_z_ctx<<<dim3(G4 / 128, NSPL_A), 128>>>(kernel_w);
    k7_gates<<<(B * U + 127) / 128, 128>>>(c, bias, out);
}

// round 6
// speedup vs baseline: 1.3182x; 1.3182x over previous
#include <cuda_runtime.h>
#include <math.h>

#define B 32
#define T 512
#define U 1024
#define E 1024
#define DIN 256
#define G4 4096        // 4*U
#define NSPL 18        // z-GEMM k-splits (2 inputs + 8 context + 8 h)
#define GRID 296       // 148 SMs x 2 resident blocks (guaranteed by launch_bounds)
#define NT 512

// ---------------- scratch (device globals: no allocations allowed) ----------
__device__ float g_qpart[16 * B * U];
__device__ float g_query[B * U];
__device__ float g_logits[B * T];
__device__ float g_attn[B * T];
__device__ float g_ctxpart[16 * B * E];
__device__ float g_context[B * E];
__device__ float g_zpart[NSPL * B * G4];
__device__ unsigned int g_count = 0;  // self-resets every barrier
__device__ unsigned int g_gen = 0;    // monotonic across launches/replays

// ---------------- helpers ----------------------------------------------------
__device__ __forceinline__ unsigned long long pack2(float a, float b) {
    unsigned long long r;
    asm("mov.b64 %0, {%1, %2};" : "=l"(r) : "r"(__float_as_uint(a)), "r"(__float_as_uint(b)));
    return r;
}
__device__ __forceinline__ void unpack2(unsigned long long v, float& a, float& b) {
    unsigned int lo, hi;
    asm("mov.b64 {%0, %1}, %2;" : "=r"(lo), "=r"(hi) : "l"(v));
    a = __uint_as_float(lo); b = __uint_as_float(hi);
}
__device__ __forceinline__ unsigned long long fma2(unsigned long long x,
                                                   unsigned long long y,
                                                   unsigned long long a) {
    unsigned long long d;
    asm("fma.rn.f32x2 %0, %1, %2, %3;" : "=l"(d) : "l"(x), "l"(y), "l"(a));
    return d;
}
__device__ __forceinline__ float tanh_hw(float x) {
    float y;
    asm("tanh.approx.f32 %0, %1;" : "=f"(y) : "f"(x));
    return y;
}
__device__ __forceinline__ float sigmoid_acc(float x) {
    return 1.0f / (1.0f + expf(-x));
}

// Grid-wide barrier: counter + monotonic generation. Safe across graph
// replays (g_count returns to 0 at every release; g_gen only grows).
__device__ __forceinline__ void grid_barrier() {
    __syncthreads();
    if (threadIdx.x == 0) {
        __threadfence();
        unsigned int gen = atomicAdd(&g_gen, 0u);
        unsigned int arrived = atomicAdd(&g_count, 1u) + 1u;
        if (arrived == GRID) {
            g_count = 0;
            __threadfence();
            atomicAdd(&g_gen, 1u);
        } else {
            while (atomicAdd(&g_gen, 0u) == gen) { __nanosleep(64); }
        }
        __threadfence();
    }
    __syncthreads();
}

// ---------------- the whole cell in one persistent kernel ---------------------
__global__ void __launch_bounds__(NT, 2) mono_cell(
    const float* __restrict__ inputs, const float* __restrict__ h,
    const float* __restrict__ c, const float* __restrict__ se,
    const float* __restrict__ es, const float* __restrict__ Wa,
    const float* __restrict__ Wa_b, const float* __restrict__ va_w,
    const float* __restrict__ va_b, const float* __restrict__ Wk,
    const float* __restrict__ Wr, const float* __restrict__ bias,
    float* __restrict__ out)
{
    __shared__ __align__(16) float pool[128 * 36];   // 18.4KB, reused per phase
    const int tid = threadIdx.x;
    const int bx = blockIdx.x;
    const int gtid = bx * NT + tid;

    // ===== P1: query partial GEMM  h[32,1024] @ Wa[1024,1024], 16 k-splits ====
    if (bx < 64) {
        const int tile = bx >> 4, kb = bx & 15;
        const int k0 = kb * 64;
        const int jj = tid & 255, bh = tid >> 8;     // 256 u-cols x 2 b-halves
        const int u = tile * 256 + jj;

        for (int idx = tid; idx < 32 * 64; idx += NT) {
            int b = idx >> 6, k = idx & 63;
            pool[k * 36 + b] = h[b * U + k0 + k];
        }
        __syncthreads();

        unsigned long long acc[8];
#pragma unroll
        for (int p = 0; p < 8; p++) acc[p] = 0ull;

        const float* wcol = Wa + (size_t)k0 * U + u;
#pragma unroll 8
        for (int k = 0; k < 64; k++) {
            float w = wcol[(size_t)k * U];
            unsigned long long ww = pack2(w, w);
            const unsigned long long* xp =
                reinterpret_cast<const unsigned long long*>(&pool[k * 36]) + bh * 8;
#pragma unroll
            for (int p = 0; p < 8; p++) acc[p] = fma2(xp[p], ww, acc[p]);
        }

        float* outp = g_qpart + (size_t)kb * (B * U);
#pragma unroll
        for (int p = 0; p < 8; p++) {
            float a, b2; unpack2(acc[p], a, b2);
            outp[(bh * 16 + 2 * p) * U + u] = a;
            outp[(bh * 16 + 2 * p + 1) * U + u] = b2;
        }
    }
    grid_barrier();

    // ===== P1b: reduce query partials + bias ==================================
    if (gtid < B * U) {
        float s = Wa_b[gtid & (U - 1)];
#pragma unroll
        for (int kb = 0; kb < 16; kb++) s += g_qpart[kb * (B * U) + gtid];
        g_query[gtid] = s;
    }
    grid_barrier();

    // ===== P2: logits[b,t] = sum_u tanh(q[b,u]+es[b,t,u])*va[u] (warp/row) ====
    {
        const int lane = tid & 31;
        const int gwarp = bx * 16 + (tid >> 5);      // 4736 warps
        const float vb = va_b[0];
        const float4* vrow = reinterpret_cast<const float4*>(va_w);
        for (int r = gwarp; r < B * T; r += GRID * 16) {
            const int b = r >> 9;
            const float4* erow = reinterpret_cast<const float4*>(es) + (size_t)r * 256;
            const float4* qrow = reinterpret_cast<const float4*>(g_query) + b * 256;
            float4 e[8];
#pragma unroll
            for (int i = 0; i < 8; i++) e[i] = erow[lane + i * 32];
            float s = 0.f;
#pragma unroll
            for (int i = 0; i < 8; i++) {
                int u4 = lane + i * 32;
                float4 q4 = qrow[u4];
                float4 v4 = vrow[u4];
                s += tanh_hw(q4.x + e[i].x) * v4.x;
                s += tanh_hw(q4.y + e[i].y) * v4.y;
                s += tanh_hw(q4.z + e[i].z) * v4.z;
                s += tanh_hw(q4.w + e[i].w) * v4.w;
            }
#pragma unroll
            for (int o = 16; o; o >>= 1) s += __shfl_xor_sync(0xffffffffu, s, o);
            if (lane == 0) g_logits[r] = s + vb;
        }
    }
    grid_barrier();

    // ===== P3: softmax over T per batch =======================================
    if (bx < 32) {
        float* red = pool;
        const int b = bx;
        const int lane = tid & 31, wid = tid >> 5;

        float l = g_logits[b * T + tid];
        float m = l;
#pragma unroll
        for (int o = 16; o; o >>= 1) m = fmaxf(m, __shfl_xor_sync(0xffffffffu, m, o));
        if (lane == 0) red[wid] = m;
        __syncthreads();
        if (tid < 32) {
            float v = red[tid & 15];
#pragma unroll
            for (int o = 8; o; o >>= 1) v = fmaxf(v, __shfl_xor_sync(0xffffffffu, v, o));
            if (tid == 0) red[0] = v;
        }
        __syncthreads();
        float mx = red[0];
        float p = __expf(l - mx);
        float sum = p;
#pragma unroll
        for (int o = 16; o; o >>= 1) sum += __shfl_xor_sync(0xffffffffu, sum, o);
        __syncthreads();
        if (lane == 0) red[wid] = sum;
        __syncthreads();
        if (tid < 32) {
            float v = (tid < 16) ? red[tid] : 0.f;
#pragma unroll
            for (int o = 8; o; o >>= 1) v += __shfl_xor_sync(0xffffffffu, v, o);
            if (tid == 0) red[0] = v;
        }
        __syncthreads();
        g_attn[b * T + tid] = p / red[0];
    }
    grid_barrier();

    // ===== P4: context partials ctxpart[pp,b,e] (16 t-chunks of 32) ===========
    if (bx < 256) {
        const int b = bx >> 3, half = (bx >> 2) & 1, tc = bx & 3;
        const int sub = tid >> 7, e4i = tid & 127;
        const int e4 = half * 128 + e4i;
        const int t0 = tc * 128 + sub * 32;

        const float* ap = g_attn + b * T + t0;
        const float4* se4 = reinterpret_cast<const float4*>(se)
                          + ((size_t)(b * T + t0)) * 256 + e4;
        float4 acc = make_float4(0.f, 0.f, 0.f, 0.f);
#pragma unroll
        for (int i = 0; i < 32; i++) {
            float p = ap[i];
            float4 v = se4[(size_t)i * 256];
            acc.x += p * v.x; acc.y += p * v.y; acc.z += p * v.z; acc.w += p * v.w;
        }
        const int pp = tc * 4 + sub;
        reinterpret_cast<float4*>(g_ctxpart)[(size_t)(pp * B + b) * 256 + e4] = acc;
    }
    grid_barrier();

    // ===== P5: reduce context partials ========================================
    if (gtid < B * E) {
        float s = 0.f;
#pragma unroll
        for (int pp = 0; pp < 16; pp++) s += g_ctxpart[pp * (B * E) + gtid];
        g_context[gtid] = s;
    }
    grid_barrier();

    // ===== P6: z partial GEMM (16 j-tiles x 18 k-chunks of 128) ===============
    if (bx < 288) {
        const int jt = bx / 18, kb = bx - jt * 18;
        const int jj = tid & 255, bh = tid >> 8;
        const int j = jt * 256 + jj;

        const float* xsrc; int x_ld, xk0;
        const float* W;    int wk0;
        if (kb < 2)       { xsrc = inputs;    x_ld = DIN; xk0 = kb * 128;        W = Wk; wk0 = kb * 128; }
        else if (kb < 10) { xsrc = g_context; x_ld = E;   xk0 = (kb - 2) * 128;  W = Wk; wk0 = DIN + (kb - 2) * 128; }
        else              { xsrc = h;         x_ld = U;   xk0 = (kb - 10) * 128; W = Wr; wk0 = (kb - 10) * 128; }

        for (int idx = tid; idx < 32 * 128; idx += NT) {
            int b = idx >> 7, kk = idx & 127;
            pool[kk * 36 + b] = xsrc[(size_t)b * x_ld + xk0 + kk];
        }
        __syncthreads();

        unsigned long long acc[8];
#pragma unroll
        for (int p = 0; p < 8; p++) acc[p] = 0ull;

        const float* wcol = W + (size_t)wk0 * G4 + j;
#pragma unroll 8
        for (int kk = 0; kk < 128; kk++) {
            float w = wcol[(size_t)kk * G4];
            unsigned long long ww = pack2(w, w);
            const unsigned long long* xp =
                reinterpret_cast<const unsigned long long*>(&pool[kk * 36]) + bh * 8;
#pragma unroll
            for (int p = 0; p < 8; p++) acc[p] = fma2(xp[p], ww, acc[p]);
        }

        float* outp = g_zpart + (size_t)kb * (B * G4);
#pragma unroll
        for (int p = 0; p < 8; p++) {
            float a, b2; unpack2(acc[p], a, b2);
            outp[(size_t)(bh * 16 + 2 * p) * G4 + j] = a;
            outp[(size_t)(bh * 16 + 2 * p + 1) * G4 + j] = b2;
        }
    }
    grid_barrier();

    // ===== P7: reduce z partials + bias, gates, outputs =======================
    if (gtid < B * U) {
        const int b = gtid >> 10, u = gtid & (U - 1);
        float z[4];
#pragma unroll
        for (int g = 0; g < 4; g++) {
            int col = g * U + u;
            float s = bias[col];
            const float* zp = g_zpart + (size_t)b * G4 + col;
#pragma unroll
            for (int kb = 0; kb < NSPL; kb++)
                s += zp[(size_t)kb * (B * G4)];
            z[g] = s;
        }
        float c_new = sigmoid_acc(z[1]) * c[gtid] + sigmoid_acc(z[0]) * tanhf(z[2]);
        float h_new = sigmoid_acc(z[3]) * tanhf(c_new);
        out[gtid]             = h_new;  // lstmout
        out[B * U + gtid]     = h_new;  // h state
        out[2 * B * U + gtid] = c_new;  // c state
    }
}

// ---------------- launcher ------------------------------------------------------
extern "C" void kernel_launch(void* const* d_in, const int* in_sizes, int n_in,
                              void* d_out, int out_size) {
    const float* inputs      = (const float*)d_in[0];
    const float* h           = (const float*)d_in[1];
    const float* c           = (const float*)d_in[2];
    const float* speech_enc  = (const float*)d_in[3];
    const float* encodestate = (const float*)d_in[4];
    const float* Wa_w        = (const float*)d_in[5];
    const float* Wa_b        = (const float*)d_in[6];
    const float* va_w        = (const float*)d_in[7];
    const float* va_b        = (const float*)d_in[8];
    const float* kernel_w    = (const float*)d_in[9];
    const float* rec_kernel  = (const float*)d_in[10];
    const float* bias        = (const float*)d_in[11];
    float* out = (float*)d_out;

    mono_cell<<<GRID, NT>>>(inputs, h, c, speech_enc, encodestate,
                            Wa_w, Wa_b, va_w, va_b,
                            kernel_w, rec_kernel, bias, out);
}